// round 4
// baseline (speedup 1.0000x reference)
#include <cuda_runtime.h>

// Problem constants (fixed by the reference)
#define RAYS   32768
#define NS     128      // samples per ray
#define IN_DIR 16
#define HID    8
#define RPB    4        // rays per block

// Inputs (metadata order):
//  d_in[0] x          int32  [B, N, 2]
//  d_in[1] d          float  [B, 16]
//  d_in[2] gridWeight float  [16777216, 4]
//  d_in[3] W0         float  [22, 8]
//  d_in[4] W1         float  [8, 3]
// Output: sigma [B, N] then rgb [B, 3], concatenated, float32.
//
// Model from R1-R3:
//   128B fills: 800 MB traffic, bytes-bound at 5.85 TB/s  -> 135 us
//   32B  fills: 296 MB traffic, but with 2 gathers/thread the kernel is
//               outstanding-miss (MLP) bound: DRAM only 23% busy -> 158 us
// Fix: 32B fills AND 8 independent gathers per thread (4 rays/block).

struct _L2GranInit {
    _L2GranInit() { cudaDeviceSetLimit(cudaLimitMaxL2FetchGranularity, 32); }
};
static _L2GranInit _l2_gran_init;

__global__ __launch_bounds__(128) void surf_kernel(
    const int2*  __restrict__ x,        // [B*N] pairs
    const float* __restrict__ d,        // [B,16]
    const float4* __restrict__ grid,    // [TABLE] rows of 4
    const float* __restrict__ W0,       // [22,8] row-major
    const float* __restrict__ W1,       // [8,3]  row-major
    float* __restrict__ out_sigma,      // [B,N]
    float* __restrict__ out_rgb)        // [B,3]
{
    const int b0   = blockIdx.x * RPB;  // rays b0 .. b0+3
    const int n    = threadIdx.x;       // 0..127 = sample index
    const int lane = n & 31;
    const int wid  = n >> 5;

    __shared__ float sW0g[6][HID];      // W0 rows 16..21 (geo part)
    __shared__ float sW1[HID][3];
    __shared__ float sBase[RPB][HID];   // per-ray d-row @ W0[0:16]
    __shared__ float sWarpProd[RPB][4];
    __shared__ float sRgb[RPB][4][3];

    // ---- issue ALL 8 random gathers first: this is the whole game ----
    int2 idx[RPB];
    #pragma unroll
    for (int r = 0; r < RPB; ++r)
        idx[r] = __ldcs(x + (size_t)(b0 + r) * NS + n);

    float4 g0[RPB], g1[RPB];
    #pragma unroll
    for (int r = 0; r < RPB; ++r) {
        g0[r] = __ldg(grid + idx[r].x);
        g1[r] = __ldg(grid + idx[r].y);
    }

    // Cooperative setup overlaps gather latency
    if (n < 48) {
        sW0g[n >> 3][n & 7] = W0[(16 + (n >> 3)) * HID + (n & 7)];
    } else if (n >= 64 && n < 88) {
        int t = n - 64;
        sW1[t / 3][t % 3] = W1[t];
    } else if (n >= 96 && n < 96 + RPB * HID) {
        int t = n - 96;          // 0..31
        int r = t >> 3;          // ray select
        int j = t & 7;
        const float* dd = d + (size_t)(b0 + r) * IN_DIR;
        float acc = 0.f;
        #pragma unroll
        for (int k = 0; k < IN_DIR; ++k) acc = fmaf(dd[k], W0[k * HID + j], acc);
        sBase[r][j] = acc;
    }
    __syncthreads();

    float sig[RPB], c[RPB][3];
    #pragma unroll
    for (int r = 0; r < RPB; ++r) {
        sig[r] = 1.f / (1.f + __expf(-(g0[r].x * g1[r].x)));
        __stcs(out_sigma + (size_t)(b0 + r) * NS + n, sig[r]);

        float h[HID];
        #pragma unroll
        for (int j = 0; j < HID; ++j) {
            float a = sBase[r][j];
            a = fmaf(g0[r].y, sW0g[0][j], a);
            a = fmaf(g0[r].z, sW0g[1][j], a);
            a = fmaf(g0[r].w, sW0g[2][j], a);
            a = fmaf(g1[r].y, sW0g[3][j], a);
            a = fmaf(g1[r].z, sW0g[4][j], a);
            a = fmaf(g1[r].w, sW0g[5][j], a);
            h[j] = fmaxf(a, 0.f);
        }
        float c0 = 0.f, c1 = 0.f, c2 = 0.f;
        #pragma unroll
        for (int j = 0; j < HID; ++j) {
            c0 = fmaf(h[j], sW1[j][0], c0);
            c1 = fmaf(h[j], sW1[j][1], c1);
            c2 = fmaf(h[j], sW1[j][2], c2);
        }
        c[r][0] = 1.f / (1.f + __expf(-c0));
        c[r][1] = 1.f / (1.f + __expf(-c1));
        c[r][2] = 1.f / (1.f + __expf(-c2));
    }

    // ---- exclusive prefix product of (1 - sigma) per ray ----
    float pe[RPB];
    #pragma unroll
    for (int r = 0; r < RPB; ++r) {
        float p = 1.f - sig[r];
        #pragma unroll
        for (int off = 1; off < 32; off <<= 1) {
            float v = __shfl_up_sync(0xffffffffu, p, off);
            if (lane >= off) p *= v;
        }
        if (lane == 31) sWarpProd[r][wid] = p;         // inclusive warp total
        pe[r] = __shfl_up_sync(0xffffffffu, p, 1);     // exclusive within warp
        if (lane == 0) pe[r] = 1.f;
    }
    __syncthreads();

    #pragma unroll
    for (int r = 0; r < RPB; ++r) {
        float prefix = 1.f;
        #pragma unroll
        for (int wnum = 0; wnum < 4; ++wnum)
            if (wnum < wid) prefix *= sWarpProd[r][wnum];
        const float w = pe[r] * prefix * sig[r];

        float r0 = w * c[r][0], r1 = w * c[r][1], r2 = w * c[r][2];
        #pragma unroll
        for (int off = 16; off > 0; off >>= 1) {
            r0 += __shfl_down_sync(0xffffffffu, r0, off);
            r1 += __shfl_down_sync(0xffffffffu, r1, off);
            r2 += __shfl_down_sync(0xffffffffu, r2, off);
        }
        if (lane == 0) { sRgb[r][wid][0] = r0; sRgb[r][wid][1] = r1; sRgb[r][wid][2] = r2; }
    }
    __syncthreads();

    if (n < RPB) {   // thread r -> ray b0+r
        float a0 = sRgb[n][0][0] + sRgb[n][1][0] + sRgb[n][2][0] + sRgb[n][3][0];
        float a1 = sRgb[n][0][1] + sRgb[n][1][1] + sRgb[n][2][1] + sRgb[n][3][1];
        float a2 = sRgb[n][0][2] + sRgb[n][1][2] + sRgb[n][2][2] + sRgb[n][3][2];
        float* o = out_rgb + (size_t)(b0 + n) * 3;
        o[0] = a0; o[1] = a1; o[2] = a2;
    }
}

extern "C" void kernel_launch(void* const* d_in, const int* in_sizes, int n_in,
                              void* d_out, int out_size) {
    const int2*  x    = (const int2*)d_in[0];
    const float* d    = (const float*)d_in[1];
    const float4* gw  = (const float4*)d_in[2];
    const float* W0   = (const float*)d_in[3];
    const float* W1   = (const float*)d_in[4];
    float* out_sigma  = (float*)d_out;
    float* out_rgb    = out_sigma + (size_t)RAYS * NS;

    surf_kernel<<<RAYS / RPB, 128>>>(x, d, gw, W0, W1, out_sigma, out_rgb);
}